// round 6
// baseline (speedup 1.0000x reference)
#include <cuda_runtime.h>
#include <cuda_bf16.h>
#include <math.h>
#include <stdint.h>

// Problem constants
#define BB 2
#define SS 4096
#define DD 256
#define HH 8
#define DHH 32
#define DMM 1024
#define MM (BB*SS)   // 8192

// ---------------- scratch (device globals, allocation-free) ----------------
__device__ float g_xn  [MM*DD];
__device__ float g_q   [MM*DD];
__device__ float g_k   [MM*DD];
__device__ float g_v   [MM*DD];
__device__ float g_attn[MM*DD];
__device__ float g_res [MM*DD];
__device__ float g_hid [MM*DMM];

// weight hi/lo bf16 buffers
__device__ __nv_bfloat16 g_wq_h[DD*DD],  g_wq_l[DD*DD];
__device__ __nv_bfloat16 g_wk_h[DD*DD],  g_wk_l[DD*DD];
__device__ __nv_bfloat16 g_wv_h[DD*DD],  g_wv_l[DD*DD];
__device__ __nv_bfloat16 g_wo_h[DD*DD],  g_wo_l[DD*DD];
__device__ __nv_bfloat16 g_w2_h[DMM*DD], g_w2_l[DMM*DD];
__device__ __nv_bfloat16 g_w3_h[DD*DMM], g_w3_l[DD*DMM];

// ---------------- helpers ----------------
__device__ __forceinline__ uint32_t smem_u32(const void* p) {
    return (uint32_t)__cvta_generic_to_shared(p);
}
__device__ __forceinline__ uint32_t pack_bf16f(float a, float b) {
    __nv_bfloat162 t = __floats2bfloat162_rn(a, b);
    return *reinterpret_cast<uint32_t*>(&t);
}
__device__ __forceinline__ float bf16_hi(float x) {
    return __bfloat162float(__float2bfloat16_rn(x));
}
__device__ __forceinline__ void split_store(__nv_bfloat16* hi, __nv_bfloat16* lo,
                                            float a, float b) {
    float ha = bf16_hi(a), hb = bf16_hi(b);
    *reinterpret_cast<uint32_t*>(hi) = pack_bf16f(ha, hb);
    *reinterpret_cast<uint32_t*>(lo) = pack_bf16f(a - ha, b - hb);
}
__device__ __forceinline__ void mma16816(float* c, const uint32_t* a,
                                         uint32_t b0, uint32_t b1) {
    asm volatile(
        "mma.sync.aligned.m16n8k16.row.col.f32.bf16.bf16.f32 "
        "{%0,%1,%2,%3}, {%4,%5,%6,%7}, {%8,%9}, {%0,%1,%2,%3};"
        : "+f"(c[0]), "+f"(c[1]), "+f"(c[2]), "+f"(c[3])
        : "r"(a[0]), "r"(a[1]), "r"(a[2]), "r"(a[3]), "r"(b0), "r"(b1));
}
__device__ __forceinline__ void ldsm_x4_t(uint32_t& r0, uint32_t& r1,
                                          uint32_t& r2, uint32_t& r3, uint32_t addr) {
    asm volatile(
        "ldmatrix.sync.aligned.m8n8.x4.trans.shared.b16 {%0,%1,%2,%3}, [%4];"
        : "=r"(r0), "=r"(r1), "=r"(r2), "=r"(r3) : "r"(addr));
}

// ---------------- weight split conversion ----------------
__global__ void conv_kernel(const float* __restrict__ src,
                            __nv_bfloat16* __restrict__ hi,
                            __nv_bfloat16* __restrict__ lo, int n)
{
    int i = blockIdx.x * blockDim.x + threadIdx.x;
    if (i >= n) return;
    float x = src[i];
    float h = bf16_hi(x);
    hi[i] = __float2bfloat16_rn(h);
    lo[i] = __float2bfloat16_rn(x - h);
}

// ---------------- LayerNorm ----------------
__global__ void ln_kernel(const float* __restrict__ x,
                          const float* __restrict__ g,
                          const float* __restrict__ b,
                          float* __restrict__ out)
{
    int row = blockIdx.x;
    int tid = threadIdx.x;
    const float* xr = x + (size_t)row * DD;
    float v = xr[tid];
    float s = v, s2 = v * v;
    #pragma unroll
    for (int off = 16; off > 0; off >>= 1) {
        s  += __shfl_down_sync(0xffffffffu, s,  off);
        s2 += __shfl_down_sync(0xffffffffu, s2, off);
    }
    __shared__ float ws[8], ws2[8];
    __shared__ float s_mu, s_rstd;
    int wid = tid >> 5, lane = tid & 31;
    if (lane == 0) { ws[wid] = s; ws2[wid] = s2; }
    __syncthreads();
    if (tid == 0) {
        float ts = 0.f, ts2 = 0.f;
        #pragma unroll
        for (int i = 0; i < 8; i++) { ts += ws[i]; ts2 += ws2[i]; }
        float mu = ts * (1.0f / DD);
        float var = ts2 * (1.0f / DD) - mu * mu;
        s_mu = mu;
        s_rstd = rsqrtf(var + 1e-5f);
    }
    __syncthreads();
    out[(size_t)row * DD + tid] = (v - s_mu) * s_rstd * g[tid] + b[tid];
}

// ================= Tensor-core GEMM: C[M,N] = A[M,K] @ W[N,K]^T =============
// A fp32 split to bf16 hi/lo in smem; W pre-split in global.
// 3 split-MMAs per product: hi*hi + hi*lo + lo*hi.
// EPI: 0 = none, 1 = bias + exact GELU, 2 = bias(optional) + residual add
#define GBM 128
#define GBN 64
#define GBK 32
#define GKP 40

template<int EPI>
__global__ void __launch_bounds__(256)
gemm_mma_kernel(const float* __restrict__ A,
                const __nv_bfloat16* __restrict__ Whi,
                const __nv_bfloat16* __restrict__ Wlo,
                const float* __restrict__ bias, const float* __restrict__ res,
                float* __restrict__ C, int M, int N, int K)
{
    __shared__ __nv_bfloat16 Ahi[GBM][GKP];
    __shared__ __nv_bfloat16 Alo[GBM][GKP];
    __shared__ __nv_bfloat16 Bhi[GBN][GKP];
    __shared__ __nv_bfloat16 Blo[GBN][GKP];

    const int tid  = threadIdx.x;
    const int w    = tid >> 5, lane = tid & 31;
    const int wm   = w >> 1, wn = w & 1;            // 4x2 warps
    const int gr   = lane >> 2;
    const int gc   = (lane & 3) * 2;
    const int rm0  = blockIdx.y * GBM;
    const int cn0  = blockIdx.x * GBN;

    const int arow = tid >> 1;
    const int acol = (tid & 1) * 16;
    const int brow = tid >> 2;
    const int bcol = (tid & 3) * 8;

    float acc[2][4][4];
    #pragma unroll
    for (int mt = 0; mt < 2; mt++)
        #pragma unroll
        for (int nt = 0; nt < 4; nt++)
            #pragma unroll
            for (int i = 0; i < 4; i++) acc[mt][nt][i] = 0.f;

    for (int k0 = 0; k0 < K; k0 += GBK) {
        // stage A (fp32 -> split bf16)
        {
            const float* ap = A + (size_t)(rm0 + arow) * K + k0 + acol;
            #pragma unroll
            for (int c = 0; c < 16; c += 4) {
                float4 f = *(const float4*)(ap + c);
                split_store(&Ahi[arow][acol + c],     &Alo[arow][acol + c],     f.x, f.y);
                split_store(&Ahi[arow][acol + c + 2], &Alo[arow][acol + c + 2], f.z, f.w);
            }
        }
        // stage B (pre-split bf16 copy)
        {
            const uint4* bh = (const uint4*)(Whi + (size_t)(cn0 + brow) * K + k0 + bcol);
            const uint4* bl = (const uint4*)(Wlo + (size_t)(cn0 + brow) * K + k0 + bcol);
            *(uint4*)&Bhi[brow][bcol] = *bh;
            *(uint4*)&Blo[brow][bcol] = *bl;
        }
        __syncthreads();

        #pragma unroll
        for (int s = 0; s < 2; s++) {
            uint32_t ah[2][4], al[2][4];
            #pragma unroll
            for (int mt = 0; mt < 2; mt++) {
                int r = wm * 32 + mt * 16 + gr;
                int c = s * 16 + gc;
                ah[mt][0] = *(const uint32_t*)&Ahi[r][c];
                ah[mt][1] = *(const uint32_t*)&Ahi[r + 8][c];
                ah[mt][2] = *(const uint32_t*)&Ahi[r][c + 8];
                ah[mt][3] = *(const uint32_t*)&Ahi[r + 8][c + 8];
                al[mt][0] = *(const uint32_t*)&Alo[r][c];
                al[mt][1] = *(const uint32_t*)&Alo[r + 8][c];
                al[mt][2] = *(const uint32_t*)&Alo[r][c + 8];
                al[mt][3] = *(const uint32_t*)&Alo[r + 8][c + 8];
            }
            #pragma unroll
            for (int nt = 0; nt < 4; nt++) {
                int n = wn * 32 + nt * 8 + gr;
                int c = s * 16 + gc;
                uint32_t bh0 = *(const uint32_t*)&Bhi[n][c];
                uint32_t bh1 = *(const uint32_t*)&Bhi[n][c + 8];
                uint32_t bl0 = *(const uint32_t*)&Blo[n][c];
                uint32_t bl1 = *(const uint32_t*)&Blo[n][c + 8];
                #pragma unroll
                for (int mt = 0; mt < 2; mt++) {
                    mma16816(acc[mt][nt], ah[mt], bh0, bh1);
                    mma16816(acc[mt][nt], ah[mt], bl0, bl1);
                    mma16816(acc[mt][nt], al[mt], bh0, bh1);
                }
            }
        }
        __syncthreads();
    }

    // epilogue
    #pragma unroll
    for (int mt = 0; mt < 2; mt++) {
        #pragma unroll
        for (int half = 0; half < 2; half++) {
            int r = rm0 + wm * 32 + mt * 16 + gr + half * 8;
            #pragma unroll
            for (int nt = 0; nt < 4; nt++) {
                int cidx = cn0 + wn * 32 + nt * 8 + gc;
                float v0 = acc[mt][nt][half * 2 + 0];
                float v1 = acc[mt][nt][half * 2 + 1];
                if (EPI == 1) {
                    v0 += bias[cidx];
                    v1 += bias[cidx + 1];
                    v0 = 0.5f * v0 * (1.0f + erff(v0 * 0.70710678118654752f));
                    v1 = 0.5f * v1 * (1.0f + erff(v1 * 0.70710678118654752f));
                } else if (EPI == 2) {
                    if (bias) { v0 += bias[cidx]; v1 += bias[cidx + 1]; }
                    v0 += res[(size_t)r * N + cidx];
                    v1 += res[(size_t)r * N + cidx + 1];
                }
                *(float2*)(C + (size_t)r * N + cidx) = make_float2(v0, v1);
            }
        }
    }
}

// ---------------- RoPE ----------------
__global__ void rope_kernel(float* __restrict__ q, float* __restrict__ k)
{
    int idx = blockIdx.x * blockDim.x + threadIdx.x;
    if (idx >= MM * HH * (DHH / 2)) return;
    int i   = idx & 15;
    int h   = (idx >> 4) & 7;
    int row = idx >> 7;
    int pos = row & (SS - 1);

    float inv = __expf(-((float)(2 * i) / 32.0f) * 9.210340371976184f);
    float theta = (float)pos * inv;
    float sn, cs;
    sincosf(theta, &sn, &cs);

    size_t off = (size_t)row * DD + h * DHH + 2 * i;
    float q0 = q[off], q1 = q[off + 1];
    q[off]     = q0 * cs - q1 * sn;
    q[off + 1] = q1 * cs + q0 * sn;
    float k0 = k[off], k1 = k[off + 1];
    k[off]     = k0 * cs - k1 * sn;
    k[off + 1] = k1 * cs + k0 * sn;
}

// ======================= Tensor-core flash attention ========================
#define QT  128
#define KTT 64
#define KSP 40
#define L2E 1.4426950408889634f

// grid = (S/QT, H, B), block = 256 (8 warps, 16 query rows each)
__global__ void __launch_bounds__(256)
attn_mma_kernel(const float* __restrict__ q, const float* __restrict__ k,
                const float* __restrict__ v, float* __restrict__ o)
{
    __shared__ float Qs[QT][DHH];
    __shared__ __nv_bfloat16 Khi[KTT][KSP];
    __shared__ __nv_bfloat16 Klo[KTT][KSP];
    __shared__ __nv_bfloat16 Vhi[KTT][KSP];
    __shared__ __nv_bfloat16 Vlo[KTT][KSP];

    const int b = blockIdx.z, h = blockIdx.y;
    const int tid = threadIdx.x;
    const int w = tid >> 5, lane = tid & 31;
    const int qbase = blockIdx.x * QT;
    const int gr = lane >> 2;
    const int gc = (lane & 3) * 2;

    {
        int row = tid >> 1;
        int c0 = (tid & 1) * 16;
        const float4* src = (const float4*)(q + ((size_t)(b * SS + qbase + row)) * DD + h * DHH + c0);
        float4* dst = (float4*)&Qs[row][c0];
        dst[0] = src[0]; dst[1] = src[1]; dst[2] = src[2]; dst[3] = src[3];
    }
    __syncthreads();

    const float scale = 0.17677669529663687f;
    uint32_t qh[2][4], ql[2][4];
    #pragma unroll
    for (int s = 0; s < 2; s++) {
        #pragma unroll
        for (int i = 0; i < 4; i++) {
            int rr = w * 16 + gr + (i & 1) * 8;
            int dd = s * 16 + gc + (i >> 1) * 8;
            float x0 = Qs[rr][dd]     * scale;
            float x1 = Qs[rr][dd + 1] * scale;
            float h0 = bf16_hi(x0), h1 = bf16_hi(x1);
            qh[s][i] = pack_bf16f(h0, h1);
            ql[s][i] = pack_bf16f(x0 - h0, x1 - h1);
        }
    }

    float m0 = -1e30f, m1 = -1e30f, l0 = 0.f, l1 = 0.f;
    float of[4][4];
    #pragma unroll
    for (int i = 0; i < 4; i++)
        #pragma unroll
        for (int j = 0; j < 4; j++) of[i][j] = 0.f;

    for (int kt = 0; kt < SS; kt += KTT) {
        __syncthreads();
        {
            int row = tid >> 2;
            int f4  = tid & 3;
            const float* kp = k + ((size_t)(b * SS + kt + row)) * DD + h * DHH;
            const float* vp = v + ((size_t)(b * SS + kt + row)) * DD + h * DHH;
            #pragma unroll
            for (int half = 0; half < 2; half++) {
                int d0 = f4 * 4 + half * 16;
                float4 kf = *(const float4*)(kp + d0);
                split_store(&Khi[row][d0],     &Klo[row][d0],     kf.x, kf.y);
                split_store(&Khi[row][d0 + 2], &Klo[row][d0 + 2], kf.z, kf.w);
                float4 vf = *(const float4*)(vp + d0);
                split_store(&Vhi[row][d0],     &Vlo[row][d0],     vf.x, vf.y);
                split_store(&Vhi[row][d0 + 2], &Vlo[row][d0 + 2], vf.z, vf.w);
            }
        }
        __syncthreads();

        float sf[8][4];
        #pragma unroll
        for (int t = 0; t < 8; t++) { sf[t][0] = 0; sf[t][1] = 0; sf[t][2] = 0; sf[t][3] = 0; }

        #pragma unroll
        for (int s = 0; s < 2; s++) {
            #pragma unroll
            for (int nt = 0; nt < 8; nt++) {
                int krow = nt * 8 + gr;
                int dd = s * 16 + gc;
                uint32_t bh0 = *(const uint32_t*)&Khi[krow][dd];
                uint32_t bh1 = *(const uint32_t*)&Khi[krow][dd + 8];
                uint32_t bl0 = *(const uint32_t*)&Klo[krow][dd];
                uint32_t bl1 = *(const uint32_t*)&Klo[krow][dd + 8];
                mma16816(sf[nt], qh[s], bh0, bh1);
                mma16816(sf[nt], qh[s], bl0, bl1);
                mma16816(sf[nt], ql[s], bh0, bh1);
            }
        }

        float mx0 = -1e30f, mx1 = -1e30f;
        #pragma unroll
        for (int t = 0; t < 8; t++) {
            mx0 = fmaxf(mx0, fmaxf(sf[t][0], sf[t][1]));
            mx1 = fmaxf(mx1, fmaxf(sf[t][2], sf[t][3]));
        }
        mx0 = fmaxf(mx0, __shfl_xor_sync(0xffffffffu, mx0, 1));
        mx0 = fmaxf(mx0, __shfl_xor_sync(0xffffffffu, mx0, 2));
        mx1 = fmaxf(mx1, __shfl_xor_sync(0xffffffffu, mx1, 1));
        mx1 = fmaxf(mx1, __shfl_xor_sync(0xffffffffu, mx1, 2));
        float mn0 = fmaxf(m0, mx0), mn1 = fmaxf(m1, mx1);
        float al0 = exp2f((m0 - mn0) * L2E), al1 = exp2f((m1 - mn1) * L2E);
        m0 = mn0; m1 = mn1;
        float rs0 = 0.f, rs1 = 0.f;
        #pragma unroll
        for (int t = 0; t < 8; t++) {
            sf[t][0] = exp2f((sf[t][0] - m0) * L2E);
            sf[t][1] = exp2f((sf[t][1] - m0) * L2E);
            sf[t][2] = exp2f((sf[t][2] - m1) * L2E);
            sf[t][3] = exp2f((sf[t][3] - m1) * L2E);
            rs0 += sf[t][0] + sf[t][1];
            rs1 += sf[t][2] + sf[t][3];
        }
        rs0 += __shfl_xor_sync(0xffffffffu, rs0, 1);
        rs0 += __shfl_xor_sync(0xffffffffu, rs0, 2);
        rs1 += __shfl_xor_sync(0xffffffffu, rs1, 1);
        rs1 += __shfl_xor_sync(0xffffffffu, rs1, 2);
        l0 = l0 * al0 + rs0;
        l1 = l1 * al1 + rs1;
        #pragma unroll
        for (int dt = 0; dt < 4; dt++) {
            of[dt][0] *= al0; of[dt][1] *= al0; of[dt][2] *= al1; of[dt][3] *= al1;
        }

        #pragma unroll
        for (int ks = 0; ks < 4; ks++) {
            uint32_t pah[4], pal[4];
            #pragma unroll
            for (int half = 0; half < 2; half++) {
                float p0 = sf[2 * ks + half][0], p1 = sf[2 * ks + half][1];
                float p2 = sf[2 * ks + half][2], p3 = sf[2 * ks + half][3];
                float h0 = bf16_hi(p0), h1 = bf16_hi(p1);
                float h2 = bf16_hi(p2), h3 = bf16_hi(p3);
                pah[half * 2 + 0] = pack_bf16f(h0, h1);
                pah[half * 2 + 1] = pack_bf16f(h2, h3);
                pal[half * 2 + 0] = pack_bf16f(p0 - h0, p1 - h1);
                pal[half * 2 + 1] = pack_bf16f(p2 - h2, p3 - h3);
            }
            #pragma unroll
            for (int dp = 0; dp < 2; dp++) {
                uint32_t vh0, vh1, vh2, vh3, vl0, vl1, vl2, vl3;
                uint32_t ah = smem_u32(&Vhi[ks * 16 + (lane & 15)][dp * 16 + ((lane >> 4) << 3)]);
                uint32_t al = smem_u32(&Vlo[ks * 16 + (lane & 15)][dp * 16 + ((lane >> 4) << 3)]);
                ldsm_x4_t(vh0, vh1, vh2, vh3, ah);
                ldsm_x4_t(vl0, vl1, vl2, vl3, al);
                mma16816(of[2 * dp],     pah, vh0, vh1);
                mma16816(of[2 * dp],     pah, vl0, vl1);
                mma16816(of[2 * dp],     pal, vh0, vh1);
                mma16816(of[2 * dp + 1], pah, vh2, vh3);
                mma16816(of[2 * dp + 1], pah, vl2, vl3);
                mma16816(of[2 * dp + 1], pal, vh2, vh3);
            }
        }
    }

    float il0 = 1.f / l0, il1 = 1.f / l1;
    int row0 = b * SS + qbase + w * 16 + gr;
    #pragma unroll
    for (int dt = 0; dt < 4; dt++) {
        int col = h * DHH + dt * 8 + gc;
        float2 v0 = make_float2(of[dt][0] * il0, of[dt][1] * il0);
        float2 v1 = make_float2(of[dt][2] * il1, of[dt][3] * il1);
        *(float2*)(o + (size_t)row0 * DD + col) = v0;
        *(float2*)(o + (size_t)(row0 + 8) * DD + col) = v1;
    }
}

// ---------------- launch --------------------------------------------------
extern "C" void kernel_launch(void* const* d_in, const int* in_sizes, int n_in,
                              void* d_out, int out_size)
{
    const float* x     = (const float*)d_in[0];
    const float* Wq    = (const float*)d_in[1];
    const float* Wk    = (const float*)d_in[2];
    const float* Wv    = (const float*)d_in[3];
    const float* Wo    = (const float*)d_in[4];
    const float* ln1_g = (const float*)d_in[5];
    const float* ln1_b = (const float*)d_in[6];
    const float* ln2_g = (const float*)d_in[7];
    const float* ln2_b = (const float*)d_in[8];
    const float* W2    = (const float*)d_in[9];
    const float* b2    = (const float*)d_in[10];
    const float* W3    = (const float*)d_in[11];
    const float* b3    = (const float*)d_in[12];
    float* out = (float*)d_out;

    float *xn, *qb, *kb, *vb, *attn, *res, *hid;
    cudaGetSymbolAddress((void**)&xn,   g_xn);
    cudaGetSymbolAddress((void**)&qb,   g_q);
    cudaGetSymbolAddress((void**)&kb,   g_k);
    cudaGetSymbolAddress((void**)&vb,   g_v);
    cudaGetSymbolAddress((void**)&attn, g_attn);
    cudaGetSymbolAddress((void**)&res,  g_res);
    cudaGetSymbolAddress((void**)&hid,  g_hid);

    __nv_bfloat16 *wqh, *wql, *wkh, *wkl, *wvh, *wvl, *woh, *wol, *w2h, *w2l, *w3h, *w3l;
    cudaGetSymbolAddress((void**)&wqh, g_wq_h); cudaGetSymbolAddress((void**)&wql, g_wq_l);
    cudaGetSymbolAddress((void**)&wkh, g_wk_h); cudaGetSymbolAddress((void**)&wkl, g_wk_l);
    cudaGetSymbolAddress((void**)&wvh, g_wv_h); cudaGetSymbolAddress((void**)&wvl, g_wv_l);
    cudaGetSymbolAddress((void**)&woh, g_wo_h); cudaGetSymbolAddress((void**)&wol, g_wo_l);
    cudaGetSymbolAddress((void**)&w2h, g_w2_h); cudaGetSymbolAddress((void**)&w2l, g_w2_l);
    cudaGetSymbolAddress((void**)&w3h, g_w3_h); cudaGetSymbolAddress((void**)&w3l, g_w3_l);

    // 0. split weights to bf16 hi/lo
    conv_kernel<<<(DD*DD + 255) / 256, 256>>>(Wq, wqh, wql, DD*DD);
    conv_kernel<<<(DD*DD + 255) / 256, 256>>>(Wk, wkh, wkl, DD*DD);
    conv_kernel<<<(DD*DD + 255) / 256, 256>>>(Wv, wvh, wvl, DD*DD);
    conv_kernel<<<(DD*DD + 255) / 256, 256>>>(Wo, woh, wol, DD*DD);
    conv_kernel<<<(DMM*DD + 255) / 256, 256>>>(W2, w2h, w2l, DMM*DD);
    conv_kernel<<<(DD*DMM + 255) / 256, 256>>>(W3, w3h, w3l, DD*DMM);

    // 1. LN1
    ln_kernel<<<MM, 256>>>(x, ln1_g, ln1_b, xn);

    // 2. QKV projections (tensor cores)
    dim3 g_qkv(DD / GBN, MM / GBM);
    gemm_mma_kernel<0><<<g_qkv, 256>>>(xn, wqh, wql, nullptr, nullptr, qb, MM, DD, DD);
    gemm_mma_kernel<0><<<g_qkv, 256>>>(xn, wkh, wkl, nullptr, nullptr, kb, MM, DD, DD);
    gemm_mma_kernel<0><<<g_qkv, 256>>>(xn, wvh, wvl, nullptr, nullptr, vb, MM, DD, DD);

    // 3. RoPE
    int rope_n = MM * HH * (DHH / 2);
    rope_kernel<<<(rope_n + 255) / 256, 256>>>(qb, kb);

    // 4. Attention (tensor cores)
    dim3 g_attn_grid(SS / QT, HH, BB);
    attn_mma_kernel<<<g_attn_grid, 256>>>(qb, kb, vb, attn);

    // 5. Output projection + residual
    gemm_mma_kernel<2><<<g_qkv, 256>>>(attn, woh, wol, nullptr, x, res, MM, DD, DD);

    // 6. LN2
    ln_kernel<<<MM, 256>>>(res, ln2_g, ln2_b, xn);

    // 7. MLP up + GELU
    dim3 g_mlp1(DMM / GBN, MM / GBM);
    gemm_mma_kernel<1><<<g_mlp1, 256>>>(xn, w2h, w2l, b2, nullptr, hid, MM, DMM, DD);

    // 8. MLP down + bias + residual
    dim3 g_mlp2(DD / GBN, MM / GBM);
    gemm_mma_kernel<2><<<g_mlp2, 256>>>(hid, w3h, w3l, b3, res, out, MM, DD, DMM);
}

// round 7
// speedup vs baseline: 1.0687x; 1.0687x over previous
#include <cuda_runtime.h>
#include <cuda_bf16.h>
#include <math.h>
#include <stdint.h>

// Problem constants
#define BB 2
#define SS 4096
#define DD 256
#define HH 8
#define DHH 32
#define DMM 1024
#define MM (BB*SS)   // 8192

// ---------------- scratch (device globals, allocation-free) ----------------
__device__ float g_q   [MM*DD];
__device__ float g_k   [MM*DD];
__device__ float g_v   [MM*DD];
__device__ float g_res [MM*DD];

__device__ __nv_bfloat16 g_xnh[MM*DD],  g_xnl[MM*DD];   // LN output split
__device__ __nv_bfloat16 g_kh [MM*DD],  g_kl [MM*DD];   // rope(k) split
__device__ __nv_bfloat16 g_vh [MM*DD],  g_vl [MM*DD];   // v split
__device__ __nv_bfloat16 g_oh [MM*DD],  g_ol [MM*DD];   // attn out split
__device__ __nv_bfloat16 g_hh [MM*DMM], g_hl [MM*DMM];  // gelu out split

// weight hi/lo bf16 buffers
__device__ __nv_bfloat16 g_wq_h[DD*DD],  g_wq_l[DD*DD];
__device__ __nv_bfloat16 g_wk_h[DD*DD],  g_wk_l[DD*DD];
__device__ __nv_bfloat16 g_wv_h[DD*DD],  g_wv_l[DD*DD];
__device__ __nv_bfloat16 g_wo_h[DD*DD],  g_wo_l[DD*DD];
__device__ __nv_bfloat16 g_w2_h[DMM*DD], g_w2_l[DMM*DD];
__device__ __nv_bfloat16 g_w3_h[DD*DMM], g_w3_l[DD*DMM];

// ---------------- helpers ----------------
__device__ __forceinline__ uint32_t smem_u32(const void* p) {
    return (uint32_t)__cvta_generic_to_shared(p);
}
__device__ __forceinline__ uint32_t pack_bf16f(float a, float b) {
    __nv_bfloat162 t = __floats2bfloat162_rn(a, b);
    return *reinterpret_cast<uint32_t*>(&t);
}
__device__ __forceinline__ float bf16_hi(float x) {
    return __bfloat162float(__float2bfloat16_rn(x));
}
__device__ __forceinline__ void split_store(__nv_bfloat16* hi, __nv_bfloat16* lo,
                                            float a, float b) {
    float ha = bf16_hi(a), hb = bf16_hi(b);
    *reinterpret_cast<uint32_t*>(hi) = pack_bf16f(ha, hb);
    *reinterpret_cast<uint32_t*>(lo) = pack_bf16f(a - ha, b - hb);
}
__device__ __forceinline__ void mma16816(float* c, const uint32_t* a,
                                         uint32_t b0, uint32_t b1) {
    asm volatile(
        "mma.sync.aligned.m16n8k16.row.col.f32.bf16.bf16.f32 "
        "{%0,%1,%2,%3}, {%4,%5,%6,%7}, {%8,%9}, {%0,%1,%2,%3};"
        : "+f"(c[0]), "+f"(c[1]), "+f"(c[2]), "+f"(c[3])
        : "r"(a[0]), "r"(a[1]), "r"(a[2]), "r"(a[3]), "r"(b0), "r"(b1));
}
__device__ __forceinline__ void ldsm_x4_t(uint32_t& r0, uint32_t& r1,
                                          uint32_t& r2, uint32_t& r3, uint32_t addr) {
    asm volatile(
        "ldmatrix.sync.aligned.m8n8.x4.trans.shared.b16 {%0,%1,%2,%3}, [%4];"
        : "=r"(r0), "=r"(r1), "=r"(r2), "=r"(r3) : "r"(addr));
}
__device__ __forceinline__ void cp16(uint32_t dst, const void* src) {
    asm volatile("cp.async.cg.shared.global [%0], [%1], 16;" :: "r"(dst), "l"(src));
}
__device__ __forceinline__ void cp_commit() {
    asm volatile("cp.async.commit_group;");
}
template<int N> __device__ __forceinline__ void cp_wait() {
    asm volatile("cp.async.wait_group %0;" :: "n"(N));
}

// ---------------- weight split conversion (all 6 weights, one kernel) ------
__global__ void conv_all_kernel(const float* __restrict__ Wq, const float* __restrict__ Wk,
                                const float* __restrict__ Wv, const float* __restrict__ Wo,
                                const float* __restrict__ W2, const float* __restrict__ W3)
{
    int i = blockIdx.x * blockDim.x + threadIdx.x;
    const float* src; __nv_bfloat16 *hi, *lo; int j;
    if      (i <  65536) { src = Wq; hi = g_wq_h; lo = g_wq_l; j = i; }
    else if (i < 131072) { src = Wk; hi = g_wk_h; lo = g_wk_l; j = i - 65536; }
    else if (i < 196608) { src = Wv; hi = g_wv_h; lo = g_wv_l; j = i - 131072; }
    else if (i < 262144) { src = Wo; hi = g_wo_h; lo = g_wo_l; j = i - 196608; }
    else if (i < 524288) { src = W2; hi = g_w2_h; lo = g_w2_l; j = i - 262144; }
    else if (i < 786432) { src = W3; hi = g_w3_h; lo = g_w3_l; j = i - 524288; }
    else return;
    float x = src[j];
    float h = bf16_hi(x);
    hi[j] = __float2bfloat16_rn(h);
    lo[j] = __float2bfloat16_rn(x - h);
}

// ---------------- LayerNorm (writes split bf16) ----------------
__global__ void ln_kernel(const float* __restrict__ x,
                          const float* __restrict__ g,
                          const float* __restrict__ b,
                          __nv_bfloat16* __restrict__ oh,
                          __nv_bfloat16* __restrict__ ol)
{
    int row = blockIdx.x;
    int tid = threadIdx.x;
    const float* xr = x + (size_t)row * DD;
    float v = xr[tid];
    float s = v, s2 = v * v;
    #pragma unroll
    for (int off = 16; off > 0; off >>= 1) {
        s  += __shfl_down_sync(0xffffffffu, s,  off);
        s2 += __shfl_down_sync(0xffffffffu, s2, off);
    }
    __shared__ float ws[8], ws2[8];
    __shared__ float s_mu, s_rstd;
    int wid = tid >> 5, lane = tid & 31;
    if (lane == 0) { ws[wid] = s; ws2[wid] = s2; }
    __syncthreads();
    if (tid == 0) {
        float ts = 0.f, ts2 = 0.f;
        #pragma unroll
        for (int i = 0; i < 8; i++) { ts += ws[i]; ts2 += ws2[i]; }
        float mu = ts * (1.0f / DD);
        float var = ts2 * (1.0f / DD) - mu * mu;
        s_mu = mu;
        s_rstd = rsqrtf(var + 1e-5f);
    }
    __syncthreads();
    float y = (v - s_mu) * s_rstd * g[tid] + b[tid];
    float h = bf16_hi(y);
    size_t idx = (size_t)row * DD + tid;
    oh[idx] = __float2bfloat16_rn(h);
    ol[idx] = __float2bfloat16_rn(y - h);
}

// ================= Tensor-core GEMM: C = A @ W^T, A pre-split ==============
// EPI: 0 = plain fp32 out, 1 = bias+GELU -> split bf16 out, 2 = bias?+res -> fp32
#define GBM 128
#define GBN 64
#define GBK 32
#define GKP 40
#define GEMM_SMEM (2 * (2*(GBM*GKP) + 2*(GBN*GKP)) * 2)   // 61440 bytes

template<int EPI>
__global__ void __launch_bounds__(256)
gemm_mma_kernel(const __nv_bfloat16* __restrict__ Ahi_g,
                const __nv_bfloat16* __restrict__ Alo_g,
                const __nv_bfloat16* __restrict__ Whi,
                const __nv_bfloat16* __restrict__ Wlo,
                const float* __restrict__ bias, const float* __restrict__ res,
                float* __restrict__ C,
                __nv_bfloat16* __restrict__ Chi, __nv_bfloat16* __restrict__ Clo,
                int M, int N, int K)
{
    extern __shared__ __nv_bfloat16 smem[];
    __nv_bfloat16 (*Ah)[GBM][GKP] = (__nv_bfloat16(*)[GBM][GKP])smem;
    __nv_bfloat16 (*Al)[GBM][GKP] = Ah + 2;
    __nv_bfloat16 (*Bh)[GBN][GKP] = (__nv_bfloat16(*)[GBN][GKP])(Al + 2);
    __nv_bfloat16 (*Bl)[GBN][GKP] = Bh + 2;

    const int tid  = threadIdx.x;
    const int w    = tid >> 5, lane = tid & 31;
    const int wm   = w >> 1, wn = w & 1;
    const int gr   = lane >> 2;
    const int gc   = (lane & 3) * 2;
    const int rm0  = blockIdx.y * GBM;
    const int cn0  = blockIdx.x * GBN;

    const int arow = tid >> 1;
    const int ac   = (tid & 1) * 16;
    const int brow = tid >> 2;
    const int bc   = (tid & 3) * 8;

    auto stage = [&](int buf, int k0) {
        const __nv_bfloat16* pah = Ahi_g + (size_t)(rm0 + arow) * K + k0 + ac;
        const __nv_bfloat16* pal = Alo_g + (size_t)(rm0 + arow) * K + k0 + ac;
        cp16(smem_u32(&Ah[buf][arow][ac]),     pah);
        cp16(smem_u32(&Ah[buf][arow][ac + 8]), pah + 8);
        cp16(smem_u32(&Al[buf][arow][ac]),     pal);
        cp16(smem_u32(&Al[buf][arow][ac + 8]), pal + 8);
        cp16(smem_u32(&Bh[buf][brow][bc]), Whi + (size_t)(cn0 + brow) * K + k0 + bc);
        cp16(smem_u32(&Bl[buf][brow][bc]), Wlo + (size_t)(cn0 + brow) * K + k0 + bc);
    };

    float acc[2][4][4];
    #pragma unroll
    for (int mt = 0; mt < 2; mt++)
        #pragma unroll
        for (int nt = 0; nt < 4; nt++)
            #pragma unroll
            for (int i = 0; i < 4; i++) acc[mt][nt][i] = 0.f;

    const int nK = K / GBK;
    stage(0, 0); cp_commit();

    for (int kt = 0; kt < nK; kt++) {
        const int cur = kt & 1;
        if (kt + 1 < nK) { stage(cur ^ 1, (kt + 1) * GBK); cp_commit(); cp_wait<1>(); }
        else cp_wait<0>();
        __syncthreads();

        #pragma unroll
        for (int s = 0; s < 2; s++) {
            uint32_t ah[2][4], al[2][4];
            #pragma unroll
            for (int mt = 0; mt < 2; mt++) {
                int r = wm * 32 + mt * 16 + gr;
                int c = s * 16 + gc;
                ah[mt][0] = *(const uint32_t*)&Ah[cur][r][c];
                ah[mt][1] = *(const uint32_t*)&Ah[cur][r + 8][c];
                ah[mt][2] = *(const uint32_t*)&Ah[cur][r][c + 8];
                ah[mt][3] = *(const uint32_t*)&Ah[cur][r + 8][c + 8];
                al[mt][0] = *(const uint32_t*)&Al[cur][r][c];
                al[mt][1] = *(const uint32_t*)&Al[cur][r + 8][c];
                al[mt][2] = *(const uint32_t*)&Al[cur][r][c + 8];
                al[mt][3] = *(const uint32_t*)&Al[cur][r + 8][c + 8];
            }
            #pragma unroll
            for (int nt = 0; nt < 4; nt++) {
                int n = wn * 32 + nt * 8 + gr;
                int c = s * 16 + gc;
                uint32_t bh0 = *(const uint32_t*)&Bh[cur][n][c];
                uint32_t bh1 = *(const uint32_t*)&Bh[cur][n][c + 8];
                uint32_t bl0 = *(const uint32_t*)&Bl[cur][n][c];
                uint32_t bl1 = *(const uint32_t*)&Bl[cur][n][c + 8];
                #pragma unroll
                for (int mt = 0; mt < 2; mt++) {
                    mma16816(acc[mt][nt], ah[mt], bh0, bh1);
                    mma16816(acc[mt][nt], ah[mt], bl0, bl1);
                    mma16816(acc[mt][nt], al[mt], bh0, bh1);
                }
            }
        }
        __syncthreads();
    }

    // epilogue
    #pragma unroll
    for (int mt = 0; mt < 2; mt++) {
        #pragma unroll
        for (int half = 0; half < 2; half++) {
            int r = rm0 + wm * 32 + mt * 16 + gr + half * 8;
            #pragma unroll
            for (int nt = 0; nt < 4; nt++) {
                int cidx = cn0 + wn * 32 + nt * 8 + gc;
                float v0 = acc[mt][nt][half * 2 + 0];
                float v1 = acc[mt][nt][half * 2 + 1];
                if (EPI == 1) {
                    v0 += bias[cidx];
                    v1 += bias[cidx + 1];
                    v0 = 0.5f * v0 * (1.0f + erff(v0 * 0.70710678118654752f));
                    v1 = 0.5f * v1 * (1.0f + erff(v1 * 0.70710678118654752f));
                    split_store(&Chi[(size_t)r * N + cidx], &Clo[(size_t)r * N + cidx], v0, v1);
                } else if (EPI == 2) {
                    if (bias) { v0 += bias[cidx]; v1 += bias[cidx + 1]; }
                    v0 += res[(size_t)r * N + cidx];
                    v1 += res[(size_t)r * N + cidx + 1];
                    *(float2*)(C + (size_t)r * N + cidx) = make_float2(v0, v1);
                } else {
                    *(float2*)(C + (size_t)r * N + cidx) = make_float2(v0, v1);
                }
            }
        }
    }
}

// ---------------- RoPE + split k,v ----------------
__global__ void rope_split_kernel(float* __restrict__ q, const float* __restrict__ k,
                                  const float* __restrict__ v,
                                  __nv_bfloat16* __restrict__ kh, __nv_bfloat16* __restrict__ kl,
                                  __nv_bfloat16* __restrict__ vh, __nv_bfloat16* __restrict__ vl)
{
    int idx = blockIdx.x * blockDim.x + threadIdx.x;
    if (idx >= MM * HH * (DHH / 2)) return;
    int i   = idx & 15;
    int h   = (idx >> 4) & 7;
    int row = idx >> 7;
    int pos = row & (SS - 1);

    float inv = __expf(-((float)(2 * i) / 32.0f) * 9.210340371976184f);
    float theta = (float)pos * inv;
    float sn, cs;
    sincosf(theta, &sn, &cs);

    size_t off = (size_t)row * DD + h * DHH + 2 * i;
    float q0 = q[off], q1 = q[off + 1];
    q[off]     = q0 * cs - q1 * sn;
    q[off + 1] = q1 * cs + q0 * sn;
    float k0 = k[off], k1 = k[off + 1];
    split_store(kh + off, kl + off, k0 * cs - k1 * sn, k1 * cs + k0 * sn);
    split_store(vh + off, vl + off, v[off], v[off + 1]);
}

// ======================= Tensor-core flash attention ========================
#define QT  128
#define KTT 64
#define KSP 40
#define L2E 1.4426950408889634f
#define ATTN_SMEM (2 * 4 * KTT * KSP * 2)   // 40960 bytes (Qs overlays start)

// grid = (S/QT, H, B), block = 256
__global__ void __launch_bounds__(256)
attn_mma_kernel(const float* __restrict__ q,
                const __nv_bfloat16* __restrict__ khi, const __nv_bfloat16* __restrict__ klo,
                const __nv_bfloat16* __restrict__ vhi, const __nv_bfloat16* __restrict__ vlo,
                __nv_bfloat16* __restrict__ ohi, __nv_bfloat16* __restrict__ olo)
{
    extern __shared__ char asmem[];
    float (*Qs)[DHH] = (float(*)[DHH])asmem;   // overlays K/V buffers; used before loop
    __nv_bfloat16 (*Kh)[KTT][KSP] = (__nv_bfloat16(*)[KTT][KSP])asmem;
    __nv_bfloat16 (*Kl)[KTT][KSP] = Kh + 2;
    __nv_bfloat16 (*Vh)[KTT][KSP] = Kh + 4;
    __nv_bfloat16 (*Vl)[KTT][KSP] = Kh + 6;

    const int b = blockIdx.z, h = blockIdx.y;
    const int tid = threadIdx.x;
    const int w = tid >> 5, lane = tid & 31;
    const int qbase = blockIdx.x * QT;
    const int gr = lane >> 2;
    const int gc = (lane & 3) * 2;

    // ---- stage Q tile (in overlay region)
    {
        int row = tid >> 1;
        int c0 = (tid & 1) * 16;
        const float4* src = (const float4*)(q + ((size_t)(b * SS + qbase + row)) * DD + h * DHH + c0);
        float4* dst = (float4*)&Qs[row][c0];
        dst[0] = src[0]; dst[1] = src[1]; dst[2] = src[2]; dst[3] = src[3];
    }
    __syncthreads();

    const float scale = 0.17677669529663687f;
    uint32_t qh[2][4], ql[2][4];
    #pragma unroll
    for (int s = 0; s < 2; s++) {
        #pragma unroll
        for (int i = 0; i < 4; i++) {
            int rr = w * 16 + gr + (i & 1) * 8;
            int dd = s * 16 + gc + (i >> 1) * 8;
            float x0 = Qs[rr][dd]     * scale;
            float x1 = Qs[rr][dd + 1] * scale;
            float h0 = bf16_hi(x0), h1 = bf16_hi(x1);
            qh[s][i] = pack_bf16f(h0, h1);
            ql[s][i] = pack_bf16f(x0 - h0, x1 - h1);
        }
    }
    __syncthreads();   // Q reads done before cp.async overwrites overlay

    const int krow = tid >> 2;
    const int kc8  = (tid & 3) * 8;
    auto stage_kv = [&](int buf, int kt) {
        size_t g = ((size_t)(b * SS + kt + krow)) * DD + h * DHH + kc8;
        cp16(smem_u32(&Kh[buf][krow][kc8]), khi + g);
        cp16(smem_u32(&Kl[buf][krow][kc8]), klo + g);
        cp16(smem_u32(&Vh[buf][krow][kc8]), vhi + g);
        cp16(smem_u32(&Vl[buf][krow][kc8]), vlo + g);
    };

    float m0 = -1e30f, m1 = -1e30f, l0 = 0.f, l1 = 0.f;
    float of[4][4];
    #pragma unroll
    for (int i = 0; i < 4; i++)
        #pragma unroll
        for (int j = 0; j < 4; j++) of[i][j] = 0.f;

    const int nT = SS / KTT;
    stage_kv(0, 0); cp_commit();

    for (int t = 0; t < nT; t++) {
        const int cur = t & 1;
        if (t + 1 < nT) { stage_kv(cur ^ 1, (t + 1) * KTT); cp_commit(); cp_wait<1>(); }
        else cp_wait<0>();
        __syncthreads();

        // ---- S = Q K^T
        float sf[8][4];
        #pragma unroll
        for (int tt = 0; tt < 8; tt++) { sf[tt][0] = 0; sf[tt][1] = 0; sf[tt][2] = 0; sf[tt][3] = 0; }

        #pragma unroll
        for (int s = 0; s < 2; s++) {
            #pragma unroll
            for (int nt = 0; nt < 8; nt++) {
                int kr = nt * 8 + gr;
                int dd = s * 16 + gc;
                uint32_t bh0 = *(const uint32_t*)&Kh[cur][kr][dd];
                uint32_t bh1 = *(const uint32_t*)&Kh[cur][kr][dd + 8];
                uint32_t bl0 = *(const uint32_t*)&Kl[cur][kr][dd];
                uint32_t bl1 = *(const uint32_t*)&Kl[cur][kr][dd + 8];
                mma16816(sf[nt], qh[s], bh0, bh1);
                mma16816(sf[nt], qh[s], bl0, bl1);
                mma16816(sf[nt], ql[s], bh0, bh1);
            }
        }

        // ---- online softmax
        float mx0 = -1e30f, mx1 = -1e30f;
        #pragma unroll
        for (int tt = 0; tt < 8; tt++) {
            mx0 = fmaxf(mx0, fmaxf(sf[tt][0], sf[tt][1]));
            mx1 = fmaxf(mx1, fmaxf(sf[tt][2], sf[tt][3]));
        }
        mx0 = fmaxf(mx0, __shfl_xor_sync(0xffffffffu, mx0, 1));
        mx0 = fmaxf(mx0, __shfl_xor_sync(0xffffffffu, mx0, 2));
        mx1 = fmaxf(mx1, __shfl_xor_sync(0xffffffffu, mx1, 1));
        mx1 = fmaxf(mx1, __shfl_xor_sync(0xffffffffu, mx1, 2));
        float mn0 = fmaxf(m0, mx0), mn1 = fmaxf(m1, mx1);
        float al0 = exp2f((m0 - mn0) * L2E), al1 = exp2f((m1 - mn1) * L2E);
        m0 = mn0; m1 = mn1;
        float rs0 = 0.f, rs1 = 0.f;
        #pragma unroll
        for (int tt = 0; tt < 8; tt++) {
            sf[tt][0] = exp2f((sf[tt][0] - m0) * L2E);
            sf[tt][1] = exp2f((sf[tt][1] - m0) * L2E);
            sf[tt][2] = exp2f((sf[tt][2] - m1) * L2E);
            sf[tt][3] = exp2f((sf[tt][3] - m1) * L2E);
            rs0 += sf[tt][0] + sf[tt][1];
            rs1 += sf[tt][2] + sf[tt][3];
        }
        rs0 += __shfl_xor_sync(0xffffffffu, rs0, 1);
        rs0 += __shfl_xor_sync(0xffffffffu, rs0, 2);
        rs1 += __shfl_xor_sync(0xffffffffu, rs1, 1);
        rs1 += __shfl_xor_sync(0xffffffffu, rs1, 2);
        l0 = l0 * al0 + rs0;
        l1 = l1 * al1 + rs1;
        #pragma unroll
        for (int dt = 0; dt < 4; dt++) {
            of[dt][0] *= al0; of[dt][1] *= al0; of[dt][2] *= al1; of[dt][3] *= al1;
        }

        // ---- O += P V
        #pragma unroll
        for (int ks = 0; ks < 4; ks++) {
            uint32_t pah[4], pal[4];
            #pragma unroll
            for (int half = 0; half < 2; half++) {
                float p0 = sf[2 * ks + half][0], p1 = sf[2 * ks + half][1];
                float p2 = sf[2 * ks + half][2], p3 = sf[2 * ks + half][3];
                float h0 = bf16_hi(p0), h1 = bf16_hi(p1);
                float h2 = bf16_hi(p2), h3 = bf16_hi(p3);
                pah[half * 2 + 0] = pack_bf16f(h0, h1);
                pah[half * 2 + 1] = pack_bf16f(h2, h3);
                pal[half * 2 + 0] = pack_bf16f(p0 - h0, p1 - h1);
                pal[half * 2 + 1] = pack_bf16f(p2 - h2, p3 - h3);
            }
            #pragma unroll
            for (int dp = 0; dp < 2; dp++) {
                uint32_t vh0, vh1, vh2, vh3, vl0, vl1, vl2, vl3;
                uint32_t ah = smem_u32(&Vh[cur][ks * 16 + (lane & 15)][dp * 16 + ((lane >> 4) << 3)]);
                uint32_t al = smem_u32(&Vl[cur][ks * 16 + (lane & 15)][dp * 16 + ((lane >> 4) << 3)]);
                ldsm_x4_t(vh0, vh1, vh2, vh3, ah);
                ldsm_x4_t(vl0, vl1, vl2, vl3, al);
                mma16816(of[2 * dp],     pah, vh0, vh1);
                mma16816(of[2 * dp],     pah, vl0, vl1);
                mma16816(of[2 * dp],     pal, vh0, vh1);
                mma16816(of[2 * dp + 1], pah, vh2, vh3);
                mma16816(of[2 * dp + 1], pah, vl2, vl3);
                mma16816(of[2 * dp + 1], pal, vh2, vh3);
            }
        }
        __syncthreads();
    }

    // ---- normalize + split-write
    float il0 = 1.f / l0, il1 = 1.f / l1;
    int row0 = b * SS + qbase + w * 16 + gr;
    #pragma unroll
    for (int dt = 0; dt < 4; dt++) {
        int col = h * DHH + dt * 8 + gc;
        size_t o0 = (size_t)row0 * DD + col;
        size_t o1 = (size_t)(row0 + 8) * DD + col;
        split_store(ohi + o0, olo + o0, of[dt][0] * il0, of[dt][1] * il0);
        split_store(ohi + o1, olo + o1, of[dt][2] * il1, of[dt][3] * il1);
    }
}

// ---------------- launch --------------------------------------------------
extern "C" void kernel_launch(void* const* d_in, const int* in_sizes, int n_in,
                              void* d_out, int out_size)
{
    const float* x     = (const float*)d_in[0];
    const float* Wq    = (const float*)d_in[1];
    const float* Wk    = (const float*)d_in[2];
    const float* Wv    = (const float*)d_in[3];
    const float* Wo    = (const float*)d_in[4];
    const float* ln1_g = (const float*)d_in[5];
    const float* ln1_b = (const float*)d_in[6];
    const float* ln2_g = (const float*)d_in[7];
    const float* ln2_b = (const float*)d_in[8];
    const float* W2    = (const float*)d_in[9];
    const float* b2    = (const float*)d_in[10];
    const float* W3    = (const float*)d_in[11];
    const float* b3    = (const float*)d_in[12];
    float* out = (float*)d_out;

    float *qb, *kb, *vb, *res;
    cudaGetSymbolAddress((void**)&qb,  g_q);
    cudaGetSymbolAddress((void**)&kb,  g_k);
    cudaGetSymbolAddress((void**)&vb,  g_v);
    cudaGetSymbolAddress((void**)&res, g_res);

    __nv_bfloat16 *xnh, *xnl, *kh, *kl, *vh, *vl, *oh, *ol, *hh, *hl;
    cudaGetSymbolAddress((void**)&xnh, g_xnh); cudaGetSymbolAddress((void**)&xnl, g_xnl);
    cudaGetSymbolAddress((void**)&kh,  g_kh);  cudaGetSymbolAddress((void**)&kl,  g_kl);
    cudaGetSymbolAddress((void**)&vh,  g_vh);  cudaGetSymbolAddress((void**)&vl,  g_vl);
    cudaGetSymbolAddress((void**)&oh,  g_oh);  cudaGetSymbolAddress((void**)&ol,  g_ol);
    cudaGetSymbolAddress((void**)&hh,  g_hh);  cudaGetSymbolAddress((void**)&hl,  g_hl);

    __nv_bfloat16 *wqh, *wql, *wkh, *wkl, *wvh, *wvl, *woh, *wol, *w2h, *w2l, *w3h, *w3l;
    cudaGetSymbolAddress((void**)&wqh, g_wq_h); cudaGetSymbolAddress((void**)&wql, g_wq_l);
    cudaGetSymbolAddress((void**)&wkh, g_wk_h); cudaGetSymbolAddress((void**)&wkl, g_wk_l);
    cudaGetSymbolAddress((void**)&wvh, g_wv_h); cudaGetSymbolAddress((void**)&wvl, g_wv_l);
    cudaGetSymbolAddress((void**)&woh, g_wo_h); cudaGetSymbolAddress((void**)&wol, g_wo_l);
    cudaGetSymbolAddress((void**)&w2h, g_w2_h); cudaGetSymbolAddress((void**)&w2l, g_w2_l);
    cudaGetSymbolAddress((void**)&w3h, g_w3_h); cudaGetSymbolAddress((void**)&w3l, g_w3_l);

    // opt-in to >48KB dynamic smem for gemm kernels (idempotent)
    cudaFuncSetAttribute(gemm_mma_kernel<0>, cudaFuncAttributeMaxDynamicSharedMemorySize, GEMM_SMEM);
    cudaFuncSetAttribute(gemm_mma_kernel<1>, cudaFuncAttributeMaxDynamicSharedMemorySize, GEMM_SMEM);
    cudaFuncSetAttribute(gemm_mma_kernel<2>, cudaFuncAttributeMaxDynamicSharedMemorySize, GEMM_SMEM);

    // 0. split all weights (one kernel)
    conv_all_kernel<<<(786432 + 255) / 256, 256>>>(Wq, Wk, Wv, Wo, W2, W3);

    // 1. LN1 -> split bf16
    ln_kernel<<<MM, 256>>>(x, ln1_g, ln1_b, xnh, xnl);

    // 2. QKV projections
    dim3 g_qkv(DD / GBN, MM / GBM);
    gemm_mma_kernel<0><<<g_qkv, 256, GEMM_SMEM>>>(xnh, xnl, wqh, wql, nullptr, nullptr, qb, nullptr, nullptr, MM, DD, DD);
    gemm_mma_kernel<0><<<g_qkv, 256, GEMM_SMEM>>>(xnh, xnl, wkh, wkl, nullptr, nullptr, kb, nullptr, nullptr, MM, DD, DD);
    gemm_mma_kernel<0><<<g_qkv, 256, GEMM_SMEM>>>(xnh, xnl, wvh, wvl, nullptr, nullptr, vb, nullptr, nullptr, MM, DD, DD);

    // 3. RoPE on q,k + split k,v
    int rope_n = MM * HH * (DHH / 2);
    rope_split_kernel<<<(rope_n + 255) / 256, 256>>>(qb, kb, vb, kh, kl, vh, vl);

    // 4. Attention -> split bf16 out
    dim3 g_attn_grid(SS / QT, HH, BB);
    attn_mma_kernel<<<g_attn_grid, 256, ATTN_SMEM>>>(qb, kh, kl, vh, vl, oh, ol);

    // 5. Output projection + residual -> fp32 res
    gemm_mma_kernel<2><<<g_qkv, 256, GEMM_SMEM>>>(oh, ol, woh, wol, nullptr, x, res, nullptr, nullptr, MM, DD, DD);

    // 6. LN2 -> split bf16
    ln_kernel<<<MM, 256>>>(res, ln2_g, ln2_b, xnh, xnl);

    // 7. MLP up + GELU -> split bf16
    dim3 g_mlp1(DMM / GBN, MM / GBM);
    gemm_mma_kernel<1><<<g_mlp1, 256, GEMM_SMEM>>>(xnh, xnl, w2h, w2l, b2, nullptr, nullptr, hh, hl, MM, DMM, DD);

    // 8. MLP down + bias + residual -> out
    dim3 g_mlp2(DD / GBN, MM / GBM);
    gemm_mma_kernel<2><<<g_mlp2, 256, GEMM_SMEM>>>(hh, hl, w3h, w3l, b3, res, out, nullptr, nullptr, MM, DD, DMM);
}